// round 6
// baseline (speedup 1.0000x reference)
#include <cuda_runtime.h>

// GaussianUpsampling: out[b,c,f] = sum_j softmax_j(-0.1*(f - c_j)^2) * x[b,c,j]
//   c = cumsum(w) - 0.5*w   (bit-matches JAX associative_scan Brent-Kung tree)
// B=16, C=256, T_text=512, T_feat=4096. Masks structurally all-true.
//
// R6: (a) cumsum = warp-per-batch, __syncwarp-only (same add tree, bit-exact);
//     (b) gauss main loop reads x as pre-duplicated (x,x) 64-bit pairs from
//         smem -> no PACK movs, 11 instr/token, same conflict-free XOR swizzle.

#define NB 16
#define NC 256
#define NCH 128            // channels per CTA
#define TT 512
#define TFEAT 4096
#define DELTA_F 0.1f
#define TILE_F 32
#define NTILES (TFEAT / TILE_F)   // 128
#define MAXBAND 32
#define NTHREADS 256

__device__ float g_c[NB * TT];
__device__ int2  g_band[NB * NTILES];

#define FMA2(acc, a, b) \
  asm("fma.rn.f32x2 %0, %1, %2, %0;" : "+l"(acc) : "l"(a), "l"(b))
#define MUL2(out, a, b) \
  asm("mul.rn.f32x2 %0, %1, %2;" : "=l"(out) : "l"(a), "l"(b))
#define UNPACK2(lo, hi, in) \
  asm("mov.b64 {%0, %1}, %2;" : "=f"(lo), "=f"(hi) : "l"(in))

__device__ __forceinline__ int lower_bound_s(const float* c, float v) {
  int lo = 0, hi = TT;
  while (lo < hi) { int m = (lo + hi) >> 1; if (c[m] < v) lo = m + 1; else hi = m; }
  return lo;
}

// ---------------------------------------------------------------------------
// Warp-per-batch Brent-Kung scan (identical add tree to jax associative_scan;
// only the thread mapping differs -> bit-exact). One block, 16 warps, no
// __syncthreads. Bands computed warp-locally afterwards.
// ---------------------------------------------------------------------------
__global__ void cumsum_kernel(const float* __restrict__ w) {
  extern __shared__ float sbuf[];              // [NB][1024]
  const int warp = threadIdx.x >> 5;
  const int lane = threadIdx.x & 31;
  float* buf = sbuf + warp * 1024;
  const float* wb = w + warp * TT;

  for (int i = lane; i < TT; i += 32) buf[i] = wb[i];
  __syncwarp();

  for (int size = TT; size > 1; size >>= 1) {   // up-sweep
    int off = 1024 - 2 * size, noff = 1024 - size, half = size >> 1;
    for (int i = lane; i < half; i += 32)
      buf[noff + i] = buf[off + 2 * i] + buf[off + 2 * i + 1];
    __syncwarp();
  }
  for (int size = 2; size <= TT; size <<= 1) {  // down-sweep
    int off = 1024 - 2 * size, offp = 1024 - size, half = size >> 1;
    for (int i = lane; i < half; i += 32) {
      float sp = buf[offp + i];
      if (2 * i + 2 < size) {
        float t = sp + buf[off + 2 * i + 2];
        buf[off + 2 * i + 1] = sp;
        buf[off + 2 * i + 2] = t;
      } else {
        buf[off + 2 * i + 1] = sp;
      }
    }
    __syncwarp();
  }
  // c = scan - 0.5*w, written in place (region [0,TT)) and to global
  for (int i = lane; i < TT; i += 32) {
    float cv = buf[i] - 0.5f * wb[i];
    buf[i] = cv;
    g_c[warp * TT + i] = cv;
  }
  __syncwarp();

  // bands: 4 tiles per lane, warp-local
  for (int t = lane; t < NTILES; t += 32) {
    const float R = 18.0f;  // exp(-0.1*18^2) ~ 8e-15 relative
    float tmin = (float)(t * TILE_F);
    float tmax = tmin + (float)(TILE_F - 1);
    int jlo = lower_bound_s(buf, tmin - R);
    int jhi = lower_bound_s(buf, tmax + R);
    int plo = lower_bound_s(buf, tmin);
    int phi = lower_bound_s(buf, tmax);
    jlo = min(jlo, max(plo - 1, 0));          // always include nearest tokens
    jhi = max(jhi, min(phi + 1, TT));
    jlo &= ~3;                                 // float4 alignment
    if (jhi - jlo > MAXBAND) {                 // statistically impossible cap
      int slack = (max(0, (plo - 1) - jlo)) & ~3;
      int need  = jhi - jlo - MAXBAND;
      int adv   = min((need + 3) & ~3, slack);
      jlo += adv;
      jhi = min(jhi, jlo + MAXBAND);
    }
    g_band[warp * NTILES + t] = make_int2(jlo, jhi);
  }
}

// ---------------------------------------------------------------------------
// Fused banded softmax + GEMM. Block = (32-frame tile, channel half, batch).
// 256 threads, thread tile 2 channels x 8 frames, regs <= 64, 4 CTAs/SM.
// x_s2 rows: 64 units of 16B, unit u holds channels (2u, 2u+1) each
// DUPLICATED: floats (x0,x0,x1,x1). Physical unit = u ^ (row>>2).
// ---------------------------------------------------------------------------
__global__ __launch_bounds__(NTHREADS, 4) void gauss_kernel(
    const float* __restrict__ x, float* __restrict__ out)
{
  __shared__ __align__(16) float x_s2[MAXBAND][2 * NCH];   // duplicated pairs
  __shared__ __align__(16) float attn_s[MAXBAND][TILE_F];  // unnormalized E
  __shared__ float ps[8][TILE_F];
  __shared__ float m_s[TILE_F];
  __shared__ __align__(16) float r_s[TILE_F];

  const int b    = blockIdx.z;
  const int half = blockIdx.y;
  const int f0   = blockIdx.x * TILE_F;
  const int tid  = threadIdx.x;

  const int2 bd = g_band[b * NTILES + blockIdx.x];
  const int jlo = bd.x;
  const int nband  = bd.y - jlo;
  const int nband4 = (nband + 3) & ~3;
  const float* cb = g_c + b * TT + jlo;

  // ---- phase A: issue x loads into registers (latency overlapped below) --
  const int cl  = tid & 3;
  const int tq  = (tid >> 2) & 7;
  const int rep = tid >> 5;          // 0..7
  const int row0 = 4 * tq;
  const bool doload = row0 < nband4;
  float v[4][4];
  if (doload) {
    const bool full = (row0 + 4 <= nband);
    const float* xb = x + ((size_t)b * NC + half * NCH) * TT + jlo + row0;
    #pragma unroll
    for (int p = 0; p < 4; p++) {
      const int c = cl + 4 * rep + 32 * p;
      const float* src = xb + (size_t)c * TT;
      if (full) {
        float4 t4 = *(const float4*)src;
        v[p][0] = t4.x; v[p][1] = t4.y; v[p][2] = t4.z; v[p][3] = t4.w;
      } else {
        v[p][0] = (row0     < nband) ? src[0] : 0.0f;
        v[p][1] = (row0 + 1 < nband) ? src[1] : 0.0f;
        v[p][2] = (row0 + 2 < nband) ? src[2] : 0.0f;
        v[p][3] = (row0 + 3 < nband) ? src[3] : 0.0f;
      }
    }
  }

  // ---- phase B: energies in registers + per-frame max ------------------
  const int fE   = tid & 31;         // frame within tile
  const int kgrp = tid >> 5;         // 0..7
  const float tf = (float)(f0 + fE);
  float e[4];
  float mloc = -1e30f;
  #pragma unroll
  for (int u = 0; u < 4; u++) {
    const int kk = kgrp + 8 * u;
    if (kk < nband) {
      float d = tf - cb[kk];
      e[u] = -DELTA_F * (d * d);
      mloc = fmaxf(mloc, e[u]);
    } else {
      e[u] = -1e30f;
    }
  }
  ps[kgrp][fE] = mloc;
  __syncthreads();                                   // A: partial maxes ready
  if (tid < TILE_F) {
    float m = ps[0][tid];
    #pragma unroll
    for (int k = 1; k < 8; k++) m = fmaxf(m, ps[k][tid]);
    m_s[tid] = m;
  }
  __syncthreads();                                   // B: m_s ready

  // ---- phase C: exp + partial sums; duplicated x STS -------------------
  {
    const float m = m_s[fE];
    float sloc = 0.0f;
    #pragma unroll
    for (int u = 0; u < 4; u++) {
      const int kk = kgrp + 8 * u;
      float E = (kk < nband) ? __expf(e[u] - m) : 0.0f;
      attn_s[kk][fE] = E;                            // lanes = 32 frames: conflict-free
      sloc += E;
    }
    ps[kgrp][fE] = sloc;
  }
  if (doload) {
    #pragma unroll
    for (int p = 0; p < 4; p++) {
      const int c  = cl + 4 * rep + 32 * p;
      const int u  = c >> 1;                         // channel-pair unit
      const int d2 = (c & 1) << 1;                   // float offset within unit
      const int pu = u ^ tq;                         // XOR swizzle
      #pragma unroll
      for (int r = 0; r < 4; r++) {
        float vv = v[p][r];
        *(float2*)&x_s2[row0 + r][4 * pu + d2] = make_float2(vv, vv);
      }
    }
  }
  __syncthreads();                                   // C: attn_s, x_s2, ps ready
  if (tid < TILE_F) {
    float s = ps[0][tid];
    #pragma unroll
    for (int k = 1; k < 8; k++) s += ps[k][tid];
    r_s[tid] = 1.0f / s;
  }

  // ---- main FMA loop (unnormalized): 3 LDS.128 + 8 FFMA2 per token -----
  const int cgrp = tid >> 2;          // 0..63: channel pair 2*cgrp, 2*cgrp+1
  const int fg   = (tid & 3) << 3;    // frame base (8 frames)

  unsigned long long acc2[2][4];
  #pragma unroll
  for (int ci = 0; ci < 2; ci++)
    #pragma unroll
    for (int q = 0; q < 4; q++) acc2[ci][q] = 0ull;

  for (int kk0 = 0; kk0 < nband4; kk0 += 4) {
    const int pu = cgrp ^ (kk0 >> 2);                // const across the quad
    #pragma unroll
    for (int u = 0; u < 4; u++) {
      const int kk = kk0 + u;
      ulonglong2 xp2 = *(const ulonglong2*)&x_s2[kk][4 * pu];  // (x0,x0),(x1,x1)
      ulonglong2 a01 = *(const ulonglong2*)&attn_s[kk][fg];
      ulonglong2 a23 = *(const ulonglong2*)&attn_s[kk][fg + 4];
      FMA2(acc2[0][0], xp2.x, a01.x);
      FMA2(acc2[0][1], xp2.x, a01.y);
      FMA2(acc2[0][2], xp2.x, a23.x);
      FMA2(acc2[0][3], xp2.x, a23.y);
      FMA2(acc2[1][0], xp2.y, a01.x);
      FMA2(acc2[1][1], xp2.y, a01.y);
      FMA2(acc2[1][2], xp2.y, a23.x);
      FMA2(acc2[1][3], xp2.y, a23.y);
    }
  }
  __syncthreads();                                   // D: r_s ready

  // ---- epilogue: normalize by r[f], store ------------------------------
  ulonglong2 r01 = *(const ulonglong2*)&r_s[fg];
  ulonglong2 r23 = *(const ulonglong2*)&r_s[fg + 4];
  unsigned long long rp[4] = {r01.x, r01.y, r23.x, r23.y};

  #pragma unroll
  for (int ci = 0; ci < 2; ci++) {
    float r[8];
    #pragma unroll
    for (int q = 0; q < 4; q++) {
      unsigned long long t;
      MUL2(t, acc2[ci][q], rp[q]);
      UNPACK2(r[2 * q], r[2 * q + 1], t);
    }
    const int ch = half * NCH + 2 * cgrp + ci;
    float* o = out + ((size_t)b * NC + ch) * TFEAT + f0 + fg;
    *(float4*)&o[0] = make_float4(r[0], r[1], r[2], r[3]);
    *(float4*)&o[4] = make_float4(r[4], r[5], r[6], r[7]);
  }
}

extern "C" void kernel_launch(void* const* d_in, const int* in_sizes, int n_in,
                              void* d_out, int out_size) {
  const float* x = (const float*)d_in[0];   // (B, C, T_text) fp32
  const float* w = (const float*)d_in[1];   // (B, T_text)    fp32
  float* out = (float*)d_out;               // (B, C, T_feat) fp32

  const int scan_smem = NB * 1024 * sizeof(float);   // 64 KB
  cudaFuncSetAttribute(cumsum_kernel, cudaFuncAttributeMaxDynamicSharedMemorySize, scan_smem);

  cumsum_kernel<<<1, NB * 32, scan_smem>>>(w);
  gauss_kernel<<<dim3(NTILES, 2, NB), NTHREADS>>>(x, out);
}

// round 7
// speedup vs baseline: 1.0986x; 1.0986x over previous
#include <cuda_runtime.h>

// GaussianUpsampling: out[b,c,f] = sum_j softmax_j(-0.1*(f - c_j)^2) * x[b,c,j]
//   c = cumsum(w) - 0.5*w   (bit-matches JAX associative_scan Brent-Kung tree)
// B=16, C=256, T_text=512, T_feat=4096. Masks structurally all-true.
//
// R7: gauss = R5 (best measured: 37.1us ncu). cumsum = one warp per block,
// 16 blocks (parallel across SMs), warp-synchronous Brent-Kung, bit-exact.

#define NB 16
#define NC 256
#define NCH 128            // channels per CTA
#define TT 512
#define TFEAT 4096
#define DELTA_F 0.1f
#define TILE_F 32
#define NTILES (TFEAT / TILE_F)   // 128
#define MAXBAND 32
#define NTHREADS 256

__device__ float g_c[NB * TT];
__device__ int2  g_band[NB * NTILES];

#define FMA2(acc, a, b) \
  asm("fma.rn.f32x2 %0, %1, %2, %0;" : "+l"(acc) : "l"(a), "l"(b))
#define MUL2(out, a, b) \
  asm("mul.rn.f32x2 %0, %1, %2;" : "=l"(out) : "l"(a), "l"(b))
#define PACK2(out, lo, hi) \
  asm("mov.b64 %0, {%1, %2};" : "=l"(out) : "f"(lo), "f"(hi))
#define UNPACK2(lo, hi, in) \
  asm("mov.b64 {%0, %1}, %2;" : "=f"(lo), "=f"(hi) : "l"(in))

__device__ __forceinline__ int lower_bound_s(const float* c, float v) {
  int lo = 0, hi = TT;
  while (lo < hi) { int m = (lo + hi) >> 1; if (c[m] < v) lo = m + 1; else hi = m; }
  return lo;
}

// ---------------------------------------------------------------------------
// Warp-synchronous Brent-Kung scan, one batch per block (16 blocks run on
// 16 SMs). Identical add tree to jax associative_scan -> bit-exact.
// ---------------------------------------------------------------------------
__global__ __launch_bounds__(32) void cumsum_kernel(const float* __restrict__ w) {
  __shared__ float buf[1024];
  const int b    = blockIdx.x;
  const int lane = threadIdx.x;
  const float* wb = w + b * TT;

  for (int i = lane; i < TT; i += 32) buf[i] = wb[i];
  __syncwarp();

  for (int size = TT; size > 1; size >>= 1) {   // up-sweep
    int off = 1024 - 2 * size, noff = 1024 - size, half = size >> 1;
    for (int i = lane; i < half; i += 32)
      buf[noff + i] = buf[off + 2 * i] + buf[off + 2 * i + 1];
    __syncwarp();
  }
  for (int size = 2; size <= TT; size <<= 1) {  // down-sweep
    int off = 1024 - 2 * size, offp = 1024 - size, half = size >> 1;
    for (int i = lane; i < half; i += 32) {
      float sp = buf[offp + i];
      if (2 * i + 2 < size) {
        float t = sp + buf[off + 2 * i + 2];
        buf[off + 2 * i + 1] = sp;
        buf[off + 2 * i + 2] = t;
      } else {
        buf[off + 2 * i + 1] = sp;
      }
    }
    __syncwarp();
  }
  // c = scan - 0.5*w, in place (region [0,TT)) and to global
  for (int i = lane; i < TT; i += 32) {
    float cv = buf[i] - 0.5f * wb[i];
    buf[i] = cv;
    g_c[b * TT + i] = cv;
  }
  __syncwarp();

  // bands: 4 tiles per lane, warp-local
  for (int t = lane; t < NTILES; t += 32) {
    const float R = 18.0f;  // exp(-0.1*18^2) ~ 8e-15 relative
    float tmin = (float)(t * TILE_F);
    float tmax = tmin + (float)(TILE_F - 1);
    int jlo = lower_bound_s(buf, tmin - R);
    int jhi = lower_bound_s(buf, tmax + R);
    int plo = lower_bound_s(buf, tmin);
    int phi = lower_bound_s(buf, tmax);
    jlo = min(jlo, max(plo - 1, 0));          // always include nearest tokens
    jhi = max(jhi, min(phi + 1, TT));
    jlo &= ~3;                                 // float4 alignment
    if (jhi - jlo > MAXBAND) {                 // statistically impossible cap
      int slack = (max(0, (plo - 1) - jlo)) & ~3;
      int need  = jhi - jlo - MAXBAND;
      int adv   = min((need + 3) & ~3, slack);
      jlo += adv;
      jhi = min(jhi, jlo + MAXBAND);
    }
    g_band[b * NTILES + t] = make_int2(jlo, jhi);
  }
}

// ---------------------------------------------------------------------------
// Fused banded softmax + GEMM (R5 version — best measured).
// Block = (32-frame tile, channel half, batch). 256 threads,
// thread tile 2 channels x 8 frames, regs <= 64, 4 CTAs/SM.
// ---------------------------------------------------------------------------
__global__ __launch_bounds__(NTHREADS, 4) void gauss_kernel(
    const float* __restrict__ x, float* __restrict__ out)
{
  __shared__ __align__(16) float x_s[MAXBAND][NCH];      // XOR-swizzled
  __shared__ __align__(16) float attn_s[MAXBAND][TILE_F]; // unnormalized E
  __shared__ float ps[8][TILE_F];
  __shared__ float m_s[TILE_F];
  __shared__ __align__(16) float r_s[TILE_F];

  const int b    = blockIdx.z;
  const int half = blockIdx.y;
  const int f0   = blockIdx.x * TILE_F;
  const int tid  = threadIdx.x;

  const int2 bd = g_band[b * NTILES + blockIdx.x];
  const int jlo = bd.x;
  const int nband  = bd.y - jlo;
  const int nband4 = (nband + 3) & ~3;
  const float* cb = g_c + b * TT + jlo;

  // ---- phase A: issue x loads into registers (latency overlapped below) --
  const int cl  = tid & 3;
  const int tq  = (tid >> 2) & 7;
  const int rep = tid >> 5;          // 0..7
  const int row0 = 4 * tq;
  const bool doload = row0 < nband4;
  float v[4][4];
  if (doload) {
    const bool full = (row0 + 4 <= nband);
    const float* xb = x + ((size_t)b * NC + half * NCH) * TT + jlo + row0;
    #pragma unroll
    for (int p = 0; p < 4; p++) {
      const int c = cl + 4 * rep + 32 * p;
      const float* src = xb + (size_t)c * TT;
      if (full) {
        float4 t4 = *(const float4*)src;
        v[p][0] = t4.x; v[p][1] = t4.y; v[p][2] = t4.z; v[p][3] = t4.w;
      } else {
        v[p][0] = (row0     < nband) ? src[0] : 0.0f;
        v[p][1] = (row0 + 1 < nband) ? src[1] : 0.0f;
        v[p][2] = (row0 + 2 < nband) ? src[2] : 0.0f;
        v[p][3] = (row0 + 3 < nband) ? src[3] : 0.0f;
      }
    }
  }

  // ---- phase B: energies in registers + per-frame max ------------------
  const int fE   = tid & 31;         // frame within tile
  const int kgrp = tid >> 5;         // 0..7
  const float tf = (float)(f0 + fE);
  float e[4];
  float mloc = -1e30f;
  #pragma unroll
  for (int u = 0; u < 4; u++) {
    const int kk = kgrp + 8 * u;
    if (kk < nband) {
      float d = tf - cb[kk];
      e[u] = -DELTA_F * (d * d);
      mloc = fmaxf(mloc, e[u]);
    } else {
      e[u] = -1e30f;
    }
  }
  ps[kgrp][fE] = mloc;
  __syncthreads();                                   // A: partial maxes ready
  if (tid < TILE_F) {
    float m = ps[0][tid];
    #pragma unroll
    for (int k = 1; k < 8; k++) m = fmaxf(m, ps[k][tid]);
    m_s[tid] = m;
  }
  __syncthreads();                                   // B: m_s ready

  // ---- phase C: exp + partial sums; x STS (LDG data long arrived) ------
  {
    const float m = m_s[fE];
    float sloc = 0.0f;
    #pragma unroll
    for (int u = 0; u < 4; u++) {
      const int kk = kgrp + 8 * u;
      float E = (kk < nband) ? __expf(e[u] - m) : 0.0f;
      attn_s[kk][fE] = E;                            // lanes = 32 frames: conflict-free
      sloc += E;
    }
    ps[kgrp][fE] = sloc;
  }
  if (doload) {
    #pragma unroll
    for (int p = 0; p < 4; p++) {
      const int cq  = rep + 8 * p;
      const int col = 4 * (cq ^ tq) + cl;            // XOR swizzle: conflict-free
      #pragma unroll
      for (int r = 0; r < 4; r++) x_s[row0 + r][col] = v[p][r];
    }
  }
  __syncthreads();                                   // C: attn_s, x_s, ps ready
  if (tid < TILE_F) {
    float s = ps[0][tid];
    #pragma unroll
    for (int k = 1; k < 8; k++) s += ps[k][tid];
    r_s[tid] = 1.0f / s;
  }

  // ---- main FMA loop (unnormalized) ------------------------------------
  const int cgrp = tid >> 2;          // 0..63: channel pair 2*cgrp, 2*cgrp+1
  const int fg   = (tid & 3) << 3;    // frame base (8 frames)

  unsigned long long acc2[2][4];
  #pragma unroll
  for (int ci = 0; ci < 2; ci++)
    #pragma unroll
    for (int q = 0; q < 4; q++) acc2[ci][q] = 0ull;

  for (int kk0 = 0; kk0 < nband4; kk0 += 4) {
    const int colb = 4 * ((cgrp >> 1) ^ (kk0 >> 2)) + 2 * (cgrp & 1);
    #pragma unroll
    for (int u = 0; u < 4; u++) {
      const int kk = kk0 + u;
      float2 xv = *(const float2*)&x_s[kk][colb];
      ulonglong2 a01 = *(const ulonglong2*)&attn_s[kk][fg];
      ulonglong2 a23 = *(const ulonglong2*)&attn_s[kk][fg + 4];
      unsigned long long xp0, xp1;
      PACK2(xp0, xv.x, xv.x);
      PACK2(xp1, xv.y, xv.y);
      FMA2(acc2[0][0], xp0, a01.x);
      FMA2(acc2[0][1], xp0, a01.y);
      FMA2(acc2[0][2], xp0, a23.x);
      FMA2(acc2[0][3], xp0, a23.y);
      FMA2(acc2[1][0], xp1, a01.x);
      FMA2(acc2[1][1], xp1, a01.y);
      FMA2(acc2[1][2], xp1, a23.x);
      FMA2(acc2[1][3], xp1, a23.y);
    }
  }
  __syncthreads();                                   // D: r_s ready

  // ---- epilogue: normalize by r[f], store ------------------------------
  ulonglong2 r01 = *(const ulonglong2*)&r_s[fg];
  ulonglong2 r23 = *(const ulonglong2*)&r_s[fg + 4];
  unsigned long long rp[4] = {r01.x, r01.y, r23.x, r23.y};

  #pragma unroll
  for (int ci = 0; ci < 2; ci++) {
    float r[8];
    #pragma unroll
    for (int q = 0; q < 4; q++) {
      unsigned long long t;
      MUL2(t, acc2[ci][q], rp[q]);
      UNPACK2(r[2 * q], r[2 * q + 1], t);
    }
    const int ch = half * NCH + 2 * cgrp + ci;
    float* o = out + ((size_t)b * NC + ch) * TFEAT + f0 + fg;
    *(float4*)&o[0] = make_float4(r[0], r[1], r[2], r[3]);
    *(float4*)&o[4] = make_float4(r[4], r[5], r[6], r[7]);
  }
}

extern "C" void kernel_launch(void* const* d_in, const int* in_sizes, int n_in,
                              void* d_out, int out_size) {
  const float* x = (const float*)d_in[0];   // (B, C, T_text) fp32
  const float* w = (const float*)d_in[1];   // (B, T_text)    fp32
  float* out = (float*)d_out;               // (B, C, T_feat) fp32

  cumsum_kernel<<<NB, 32>>>(w);
  gauss_kernel<<<dim3(NTILES, 2, NB), NTHREADS>>>(x, out);
}

// round 8
// speedup vs baseline: 1.2548x; 1.1421x over previous
#include <cuda_runtime.h>

// GaussianUpsampling: out[b,c,f] = sum_j softmax_j(-0.1*(f - c_j)^2) * x[b,c,j]
//   c = cumsum(w) - 0.5*w   (bit-matches JAX associative_scan Brent-Kung tree)
// B=16, C=256, T_text=512, T_feat=4096. Masks structurally all-true.
//
// R8: cumsum = R5 block version (best measured). Gauss: softmax max computed
// analytically per frame (nearest band center via 5-step warp-local binary
// search) -> phase-B reduction and 2 of 4 block barriers removed.

#define NB 16
#define NC 256
#define NCH 128            // channels per CTA
#define TT 512
#define TFEAT 4096
#define DELTA_F 0.1f
#define TILE_F 32
#define NTILES (TFEAT / TILE_F)   // 128
#define MAXBAND 32
#define NTHREADS 256

__device__ float g_c[NB * TT];
__device__ int2  g_band[NB * NTILES];

#define FMA2(acc, a, b) \
  asm("fma.rn.f32x2 %0, %1, %2, %0;" : "+l"(acc) : "l"(a), "l"(b))
#define MUL2(out, a, b) \
  asm("mul.rn.f32x2 %0, %1, %2;" : "=l"(out) : "l"(a), "l"(b))
#define PACK2(out, lo, hi) \
  asm("mov.b64 %0, {%1, %2};" : "=l"(out) : "f"(lo), "f"(hi))
#define UNPACK2(lo, hi, in) \
  asm("mov.b64 {%0, %1}, %2;" : "=f"(lo), "=f"(hi) : "l"(in))

__device__ __forceinline__ int lower_bound_s(const float* c, float v) {
  int lo = 0, hi = TT;
  while (lo < hi) { int m = (lo + hi) >> 1; if (c[m] < v) lo = m + 1; else hi = m; }
  return lo;
}

// ---------------------------------------------------------------------------
// Brent-Kung scan replicating jax.lax.associative_scan's exact add tree,
// then per-tile band computation. 16 blocks x 256 threads (R5 version).
// ---------------------------------------------------------------------------
__global__ void cumsum_kernel(const float* __restrict__ w) {
  __shared__ float buf[1024];
  __shared__ float c_sh[TT];
  const int b = blockIdx.x;
  const int tid = threadIdx.x;
  const float* wb = w + b * TT;

  for (int i = tid; i < TT; i += blockDim.x) buf[i] = wb[i];
  __syncthreads();

  for (int size = TT; size > 1; size >>= 1) {   // up-sweep
    int off = 1024 - 2 * size, noff = 1024 - size, half = size >> 1;
    for (int i = tid; i < half; i += blockDim.x)
      buf[noff + i] = buf[off + 2 * i] + buf[off + 2 * i + 1];
    __syncthreads();
  }
  for (int size = 2; size <= TT; size <<= 1) {  // down-sweep
    int off = 1024 - 2 * size, offp = 1024 - size, half = size >> 1;
    for (int i = tid; i < half; i += blockDim.x) {
      float sp = buf[offp + i];
      if (2 * i + 2 < size) {
        float t = sp + buf[off + 2 * i + 2];
        buf[off + 2 * i + 1] = sp;
        buf[off + 2 * i + 2] = t;
      } else {
        buf[off + 2 * i + 1] = sp;
      }
    }
    __syncthreads();
  }
  for (int i = tid; i < TT; i += blockDim.x) {
    float cv = buf[i] - 0.5f * wb[i];
    c_sh[i] = cv;
    g_c[b * TT + i] = cv;
  }
  __syncthreads();

  for (int t = tid; t < NTILES; t += blockDim.x) {
    const float R = 18.0f;  // exp(-0.1*18^2) ~ 8e-15 relative
    float tmin = (float)(t * TILE_F);
    float tmax = tmin + (float)(TILE_F - 1);
    int jlo = lower_bound_s(c_sh, tmin - R);
    int jhi = lower_bound_s(c_sh, tmax + R);
    int plo = lower_bound_s(c_sh, tmin);
    int phi = lower_bound_s(c_sh, tmax);
    jlo = min(jlo, max(plo - 1, 0));          // always include nearest tokens
    jhi = max(jhi, min(phi + 1, TT));
    jlo &= ~3;                                 // float4 alignment
    if (jhi - jlo > MAXBAND) {                 // statistically impossible cap
      int slack = (max(0, (plo - 1) - jlo)) & ~3;
      int need  = jhi - jlo - MAXBAND;
      int adv   = min((need + 3) & ~3, slack);
      jlo += adv;
      jhi = min(jhi, jlo + MAXBAND);
    }
    g_band[b * NTILES + t] = make_int2(jlo, jhi);
  }
}

// ---------------------------------------------------------------------------
// Fused banded softmax + GEMM. Block = (32-frame tile, channel half, batch).
// 256 threads, thread tile 2 channels x 8 frames, regs <= 64, 4 CTAs/SM.
// Softmax max = energy of nearest band center (exact), found by warp-local
// binary search -> no cross-warp max reduction.
// ---------------------------------------------------------------------------
__global__ __launch_bounds__(NTHREADS, 4) void gauss_kernel(
    const float* __restrict__ x, float* __restrict__ out)
{
  __shared__ __align__(16) float x_s[MAXBAND][NCH];      // XOR-swizzled
  __shared__ __align__(16) float attn_s[MAXBAND][TILE_F]; // unnormalized E
  __shared__ float c_sh[MAXBAND];
  __shared__ float ps[8][TILE_F];
  __shared__ __align__(16) float r_s[TILE_F];

  const int b    = blockIdx.z;
  const int half = blockIdx.y;
  const int f0   = blockIdx.x * TILE_F;
  const int tid  = threadIdx.x;

  const int2 bd = g_band[b * NTILES + blockIdx.x];
  const int jlo = bd.x;
  const int nband  = bd.y - jlo;
  const int nband4 = (nband + 3) & ~3;

  // ---- phase A: issue x loads into registers (latency overlapped below) --
  const int cl  = tid & 3;
  const int tq  = (tid >> 2) & 7;
  const int rep = tid >> 5;          // 0..7
  const int row0 = 4 * tq;
  const bool doload = row0 < nband4;
  float v[4][4];
  if (doload) {
    const bool full = (row0 + 4 <= nband);
    const float* xb = x + ((size_t)b * NC + half * NCH) * TT + jlo + row0;
    #pragma unroll
    for (int p = 0; p < 4; p++) {
      const int c = cl + 4 * rep + 32 * p;
      const float* src = xb + (size_t)c * TT;
      if (full) {
        float4 t4 = *(const float4*)src;
        v[p][0] = t4.x; v[p][1] = t4.y; v[p][2] = t4.z; v[p][3] = t4.w;
      } else {
        v[p][0] = (row0     < nband) ? src[0] : 0.0f;
        v[p][1] = (row0 + 1 < nband) ? src[1] : 0.0f;
        v[p][2] = (row0 + 2 < nband) ? src[2] : 0.0f;
        v[p][3] = (row0 + 3 < nband) ? src[3] : 0.0f;
      }
    }
  }

  // band centers into smem
  if (tid < MAXBAND)
    c_sh[tid] = (tid < nband) ? g_c[b * TT + jlo + tid] : 3.0e38f;
  __syncthreads();                                   // #1: c_sh ready

  // ---- phase B: analytic softmax max + exp + partial sums; x STS -------
  const int fE   = tid & 31;         // frame within tile
  const int kgrp = tid >> 5;         // 0..7
  {
    const float tf = (float)(f0 + fE);
    // nearest center: first index with c >= tf (<=5 steps, nband <= 32)
    int lo = 0, hi = nband;
    while (lo < hi) { int mid = (lo + hi) >> 1; if (c_sh[mid] < tf) lo = mid + 1; else hi = mid; }
    float dR = (lo < nband) ? (c_sh[lo] - tf) : 3.0e38f;
    float dL = (lo > 0)     ? (tf - c_sh[lo - 1]) : 3.0e38f;
    float dmin = fminf(dL, dR);
    const float m = -DELTA_F * (dmin * dmin);        // exact max of band energies

    float sloc = 0.0f;
    #pragma unroll
    for (int u = 0; u < 4; u++) {
      const int kk = kgrp + 8 * u;
      float E = 0.0f;
      if (kk < nband) {
        float d = tf - c_sh[kk];
        float e = -DELTA_F * (d * d);
        E = __expf(e - m);                           // <= 1, NaN-safe
      }
      attn_s[kk][fE] = E;                            // lanes = 32 frames: conflict-free
      sloc += E;
    }
    ps[kgrp][fE] = sloc;
  }
  if (doload) {
    #pragma unroll
    for (int p = 0; p < 4; p++) {
      const int cq  = rep + 8 * p;
      const int col = 4 * (cq ^ tq) + cl;            // XOR swizzle: conflict-free
      #pragma unroll
      for (int r = 0; r < 4; r++) x_s[row0 + r][col] = v[p][r];
    }
  }
  __syncthreads();                                   // #2: attn_s, x_s, ps ready
  if (tid < TILE_F) {
    float s = ps[0][tid];
    #pragma unroll
    for (int k = 1; k < 8; k++) s += ps[k][tid];
    r_s[tid] = 1.0f / s;
  }

  // ---- main FMA loop (unnormalized) ------------------------------------
  const int cgrp = tid >> 2;          // 0..63: channel pair 2*cgrp, 2*cgrp+1
  const int fg   = (tid & 3) << 3;    // frame base (8 frames)

  unsigned long long acc2[2][4];
  #pragma unroll
  for (int ci = 0; ci < 2; ci++)
    #pragma unroll
    for (int q = 0; q < 4; q++) acc2[ci][q] = 0ull;

  for (int kk0 = 0; kk0 < nband4; kk0 += 4) {
    const int colb = 4 * ((cgrp >> 1) ^ (kk0 >> 2)) + 2 * (cgrp & 1);
    #pragma unroll
    for (int u = 0; u < 4; u++) {
      const int kk = kk0 + u;
      float2 xv = *(const float2*)&x_s[kk][colb];
      ulonglong2 a01 = *(const ulonglong2*)&attn_s[kk][fg];
      ulonglong2 a23 = *(const ulonglong2*)&attn_s[kk][fg + 4];
      unsigned long long xp0, xp1;
      PACK2(xp0, xv.x, xv.x);
      PACK2(xp1, xv.y, xv.y);
      FMA2(acc2[0][0], xp0, a01.x);
      FMA2(acc2[0][1], xp0, a01.y);
      FMA2(acc2[0][2], xp0, a23.x);
      FMA2(acc2[0][3], xp0, a23.y);
      FMA2(acc2[1][0], xp1, a01.x);
      FMA2(acc2[1][1], xp1, a01.y);
      FMA2(acc2[1][2], xp1, a23.x);
      FMA2(acc2[1][3], xp1, a23.y);
    }
  }
  __syncthreads();                                   // #3: r_s ready

  // ---- epilogue: normalize by r[f], store ------------------------------
  ulonglong2 r01 = *(const ulonglong2*)&r_s[fg];
  ulonglong2 r23 = *(const ulonglong2*)&r_s[fg + 4];
  unsigned long long rp[4] = {r01.x, r01.y, r23.x, r23.y};

  #pragma unroll
  for (int ci = 0; ci < 2; ci++) {
    float r[8];
    #pragma unroll
    for (int q = 0; q < 4; q++) {
      unsigned long long t;
      MUL2(t, acc2[ci][q], rp[q]);
      UNPACK2(r[2 * q], r[2 * q + 1], t);
    }
    const int ch = half * NCH + 2 * cgrp + ci;
    float* o = out + ((size_t)b * NC + ch) * TFEAT + f0 + fg;
    *(float4*)&o[0] = make_float4(r[0], r[1], r[2], r[3]);
    *(float4*)&o[4] = make_float4(r[4], r[5], r[6], r[7]);
  }
}

extern "C" void kernel_launch(void* const* d_in, const int* in_sizes, int n_in,
                              void* d_out, int out_size) {
  const float* x = (const float*)d_in[0];   // (B, C, T_text) fp32
  const float* w = (const float*)d_in[1];   // (B, T_text)    fp32
  float* out = (float*)d_out;               // (B, C, T_feat) fp32

  cumsum_kernel<<<NB, 256>>>(w);
  gauss_kernel<<<dim3(NTILES, 2, NB), NTHREADS>>>(x, out);
}